// round 1
// baseline (speedup 1.0000x reference)
#include <cuda_runtime.h>
#include <cuda_bf16.h>
#include <cstdint>

#define B_   32
#define S_   2048
#define D_   1024
#define N1_  512
#define WIN  256          // decay window: alpha underflows to exactly 0 outside
#define MT   64           // tokens per pass1 block
#define NC   128          // N-chunk of the gate GEMM
#define KC   64           // K-chunk staged in smem
#define XSTRIDE 1032      // 1024 + 8 bf16 pad (conflict-free fragment loads)
#define WSTRIDE 72        // 64 + 8 bf16 pad

// -------- persistent device scratch (no dynamic allocation allowed) --------
__device__ __nv_bfloat16 g_Wt[N1_ * D_];   // W1 transposed, bf16: [n][k]
__device__ float g_v[D_];                  // key_w @ q
__device__ float g_qkb;                    // q . key_b
__device__ int   g_len[B_];
__device__ float g_gate[B_ * WIN];
__device__ float g_logit[B_ * WIN];
__device__ float g_w[B_ * WIN];            // alpha * gate, compact window

// ---------------------------------------------------------------------------
// Kernel: detect mask dtype (u8 / int32-0,1 / float32-0,1) and compute lengths
// ---------------------------------------------------------------------------
__global__ void k_lengths(const unsigned char* __restrict__ m8) {
    __shared__ int flag_nonmono, flag_f32;
    __shared__ int cnt[B_];
    int tid = threadIdx.x;
    if (tid == 0) { flag_nonmono = 0; flag_f32 = 0; }
    if (tid < B_) cnt[tid] = 0;
    __syncthreads();

    // A right-padding bool mask viewed as u8 is nondecreasing within each row.
    // Wider-int encodings (01 00 00 00 ...) violate that -> detect.
    int nm = 0;
    for (int i = tid; i < B_ * S_ - 1; i += blockDim.x) {
        if ((i & (S_ - 1)) != (S_ - 1) && m8[i] > m8[i + 1]) nm = 1;
    }
    if (nm) atomicExch(&flag_nonmono, 1);
    __syncthreads();

    int mode = 0;  // 0=u8, 1=i32, 2=f32
    if (flag_nonmono) {
        // element size >= 4B => reading 65536 u32 is in-bounds
        const unsigned* m32 = (const unsigned*)m8;
        int f = 0;
        for (int i = tid; i < B_ * S_; i += blockDim.x)
            if (m32[i] == 0x3f800000u) f = 1;
        if (f) atomicExch(&flag_f32, 1);
        __syncthreads();
        mode = flag_f32 ? 2 : 1;
    }

    int lane = tid & 31;
    for (int b = 0; b < B_; b++) {
        int c = 0;
        for (int s = tid; s < S_; s += blockDim.x) {
            unsigned vv;
            if (mode == 0) vv = m8[b * S_ + s];
            else           vv = ((const unsigned*)m8)[b * S_ + s];
            if (vv == 0u) c++;   // False = valid
        }
        #pragma unroll
        for (int o = 16; o; o >>= 1) c += __shfl_xor_sync(0xffffffffu, c, o);
        if (lane == 0) atomicAdd(&cnt[b], c);
    }
    __syncthreads();
    if (tid < B_) g_len[tid] = cnt[tid];
}

// ---------------------------------------------------------------------------
// Kernel: transpose gate_w1 [K=1024][N=512] fp32 -> g_Wt [N][K] bf16
// ---------------------------------------------------------------------------
__global__ void k_prep_w(const float* __restrict__ w1) {
    __shared__ float t[32][33];
    int k0 = blockIdx.x * 32;          // gridDim.x = 32
    int n0 = blockIdx.y * 32;          // gridDim.y = 16
    int tx = threadIdx.x, ty = threadIdx.y;  // (32, 8)
    #pragma unroll
    for (int i = 0; i < 4; i++)
        t[ty + i * 8][tx] = w1[(k0 + ty + i * 8) * N1_ + n0 + tx];
    __syncthreads();
    #pragma unroll
    for (int i = 0; i < 4; i++)
        g_Wt[(size_t)(n0 + ty + i * 8) * D_ + k0 + tx] =
            __float2bfloat16_rn(t[tx][ty + i * 8]);
}

// ---------------------------------------------------------------------------
// Kernel: v = key_w @ q (fp32), and qkb = q . key_b (block 1024)
// ---------------------------------------------------------------------------
__global__ void k_prep_v(const float* __restrict__ kw, const float* __restrict__ q,
                         const float* __restrict__ kb) {
    int d = blockIdx.x;
    int tid = threadIdx.x;  // 128
    float p = 0.f;
    if (d < D_) {
        for (int e = tid; e < D_; e += 128) p += kw[(size_t)d * D_ + e] * q[e];
    } else {
        for (int e = tid; e < D_; e += 128) p += q[e] * kb[e];
    }
    #pragma unroll
    for (int o = 16; o; o >>= 1) p += __shfl_xor_sync(0xffffffffu, p, o);
    __shared__ float r[4];
    if ((tid & 31) == 0) r[tid >> 5] = p;
    __syncthreads();
    if (tid == 0) {
        float s = r[0] + r[1] + r[2] + r[3];
        if (d < D_) g_v[d] = s; else g_qkb = s;
    }
}

__device__ __forceinline__ float gelu_exact(float v) {
    return 0.5f * v * (1.0f + erff(v * 0.70710678118654752f));
}

// ---------------------------------------------------------------------------
// Kernel: pass 1 — fused gate-MLP GEMM + logit dot, windowed tokens only.
//   grid = 128 (32 batches x 4 tiles of 64 tokens), 256 threads.
// ---------------------------------------------------------------------------
__global__ void __launch_bounds__(256) k_pass1(
    const float* __restrict__ x, const float* __restrict__ b1,
    const float* __restrict__ w2, const float* __restrict__ b2) {
    extern __shared__ char sm_[];
    __nv_bfloat16* xs = (__nv_bfloat16*)sm_;               // [MT][XSTRIDE]
    __nv_bfloat16* ws = xs + MT * XSTRIDE;                 // [NC][WSTRIDE]
    float* xvp  = (float*)(ws + NC * WSTRIDE);             // [8][MT] partials
    float* xv   = xvp + 8 * MT;                            // [MT]
    float* gacc = xv + MT;                                 // [MT]

    int tid = threadIdx.x;
    int lane = tid & 31, warp = tid >> 5;
    int b = blockIdx.x >> 2, part = blockIdx.x & 3;
    int L = g_len[b];
    size_t t0 = (size_t)b * S_ + (size_t)(L - WIN) + (size_t)part * MT;

    if (tid < MT) { gacc[tid] = 0.f; }

    // ---- stage x tile (fp32 -> bf16) and accumulate xv = x . v in fp32 ----
    {
        int col = tid * 4;  // 256 threads x float4 = one full row
        float4 v4 = *(const float4*)&g_v[col];
        for (int r = 0; r < MT; r++) {
            float4 xr = *(const float4*)&x[(t0 + r) * D_ + col];
            __nv_bfloat162* p = (__nv_bfloat162*)&xs[r * XSTRIDE + col];
            p[0] = __floats2bfloat162_rn(xr.x, xr.y);
            p[1] = __floats2bfloat162_rn(xr.z, xr.w);
            float pt = xr.x * v4.x + xr.y * v4.y + xr.z * v4.z + xr.w * v4.w;
            #pragma unroll
            for (int o = 16; o; o >>= 1) pt += __shfl_xor_sync(0xffffffffu, pt, o);
            if (lane == 0) xvp[warp * MT + r] = pt;
        }
    }
    __syncthreads();
    if (tid < MT) {
        float s = 0.f;
        #pragma unroll
        for (int w = 0; w < 8; w++) s += xvp[w * MT + tid];
        xv[tid] = s;
    }
    __syncthreads();

    // ---- GEMM h = x @ W1 (bf16 mma.sync, fp32 accum), fused gelu*w2 ----
    int wm = warp >> 2, wn = warp & 3;   // warp grid 2(M) x 4(N)
    int g4 = lane >> 2, q = lane & 3;

    for (int nc = 0; nc < 4; nc++) {
        float c[2][4][4];
        #pragma unroll
        for (int mf = 0; mf < 2; mf++)
            #pragma unroll
            for (int nf = 0; nf < 4; nf++)
                #pragma unroll
                for (int e = 0; e < 4; e++) c[mf][nf][e] = 0.f;

        for (int kc = 0; kc < 16; kc++) {
            __syncthreads();
            for (int i = tid; i < NC * KC / 8; i += 256) {
                int n  = i >> 3;
                int k8 = (i & 7) << 3;
                *(uint4*)&ws[n * WSTRIDE + k8] =
                    *(const uint4*)&g_Wt[(size_t)(nc * NC + n) * D_ + kc * KC + k8];
            }
            __syncthreads();
            #pragma unroll
            for (int kk = 0; kk < 4; kk++) {
                int kb_ = kc * KC + kk * 16 + q * 2;
                uint32_t a[2][4];
                #pragma unroll
                for (int mf = 0; mf < 2; mf++) {
                    int r = wm * 32 + mf * 16 + g4;
                    a[mf][0] = *(const uint32_t*)&xs[r * XSTRIDE + kb_];
                    a[mf][1] = *(const uint32_t*)&xs[(r + 8) * XSTRIDE + kb_];
                    a[mf][2] = *(const uint32_t*)&xs[r * XSTRIDE + kb_ + 8];
                    a[mf][3] = *(const uint32_t*)&xs[(r + 8) * XSTRIDE + kb_ + 8];
                }
                uint32_t bb[4][2];
                int kl = kk * 16 + q * 2;
                #pragma unroll
                for (int nf = 0; nf < 4; nf++) {
                    int n = wn * 32 + nf * 8 + g4;
                    bb[nf][0] = *(const uint32_t*)&ws[n * WSTRIDE + kl];
                    bb[nf][1] = *(const uint32_t*)&ws[n * WSTRIDE + kl + 8];
                }
                #pragma unroll
                for (int mf = 0; mf < 2; mf++)
                    #pragma unroll
                    for (int nf = 0; nf < 4; nf++) {
                        asm volatile(
                            "mma.sync.aligned.m16n8k16.row.col.f32.bf16.bf16.f32 "
                            "{%0,%1,%2,%3}, {%4,%5,%6,%7}, {%8,%9}, {%0,%1,%2,%3};\n"
                            : "+f"(c[mf][nf][0]), "+f"(c[mf][nf][1]),
                              "+f"(c[mf][nf][2]), "+f"(c[mf][nf][3])
                            : "r"(a[mf][0]), "r"(a[mf][1]), "r"(a[mf][2]), "r"(a[mf][3]),
                              "r"(bb[nf][0]), "r"(bb[nf][1]));
                    }
            }
        }
        // epilogue: g[m] += sum_n gelu(h + b1[n]) * w2[n]
        #pragma unroll
        for (int mf = 0; mf < 2; mf++) {
            float lo = 0.f, hi = 0.f;
            #pragma unroll
            for (int nf = 0; nf < 4; nf++) {
                int n0 = nc * NC + wn * 32 + nf * 8 + q * 2;
                float b1a = __ldg(&b1[n0]), b1b = __ldg(&b1[n0 + 1]);
                float w2a = __ldg(&w2[n0]), w2b = __ldg(&w2[n0 + 1]);
                lo += gelu_exact(c[mf][nf][0] + b1a) * w2a
                    + gelu_exact(c[mf][nf][1] + b1b) * w2b;
                hi += gelu_exact(c[mf][nf][2] + b1a) * w2a
                    + gelu_exact(c[mf][nf][3] + b1b) * w2b;
            }
            lo += __shfl_xor_sync(0xffffffffu, lo, 1);
            lo += __shfl_xor_sync(0xffffffffu, lo, 2);
            hi += __shfl_xor_sync(0xffffffffu, hi, 1);
            hi += __shfl_xor_sync(0xffffffffu, hi, 2);
            if (q == 0) {
                int r = wm * 32 + mf * 16 + g4;
                atomicAdd(&gacc[r], lo);
                atomicAdd(&gacc[r + 8], hi);
            }
        }
    }
    __syncthreads();

    if (tid < MT) {
        float z = gacc[tid] + b2[0];
        float gate = 1.f / (1.f + expf(-z));
        int j = part * MT + tid;
        g_gate[b * WIN + j]  = gate;
        // logits = (gated . v + q.key_b) / sqrt(D);  gated.v = gate * (x.v)
        g_logit[b * WIN + j] = (gate * xv[tid] + g_qkb) * 0.03125f;
    }
}

// ---------------------------------------------------------------------------
// Kernel: window softmax with chronological decay; weights = alpha * gate
// ---------------------------------------------------------------------------
__global__ void k_softmax(const float* __restrict__ lamp) {
    int b = blockIdx.x, tid = threadIdx.x;  // 256 threads == WIN
    int lane = tid & 31, warp = tid >> 5;
    __shared__ float redm[8], reds[8];

    float lam = lamp[0];
    float pl  = fmaxf(lam, 0.f) + log1pf(expf(-fabsf(lam)));  // softplus
    float lg  = g_logit[b * WIN + tid];
    float pen = (float)(WIN - 1 - tid);   // = L-1-t inside the window
    float dec = lg - pl * pen;

    float v = dec;
    #pragma unroll
    for (int o = 16; o; o >>= 1) v = fmaxf(v, __shfl_xor_sync(0xffffffffu, v, o));
    if (lane == 0) redm[warp] = v;
    __syncthreads();
    if (warp == 0) {
        float t = redm[lane & 7];
        #pragma unroll
        for (int o = 4; o; o >>= 1) t = fmaxf(t, __shfl_xor_sync(0xffffffffu, t, o));
        if (lane == 0) redm[0] = t;
    }
    __syncthreads();
    float m = redm[0];

    float e = expf(dec - m);
    v = e;
    #pragma unroll
    for (int o = 16; o; o >>= 1) v += __shfl_xor_sync(0xffffffffu, v, o);
    if (lane == 0) reds[warp] = v;
    __syncthreads();
    if (warp == 0) {
        float t = reds[lane & 7];
        #pragma unroll
        for (int o = 4; o; o >>= 1) t += __shfl_xor_sync(0xffffffffu, t, o);
        if (lane == 0) reds[0] = t;
    }
    __syncthreads();
    float s = reds[0];

    g_w[b * WIN + tid] = g_gate[b * WIN + tid] * e / s;
}

// ---------------------------------------------------------------------------
// Kernel: scene[b,d] = sum_{window} w * x[b,s,d]
// ---------------------------------------------------------------------------
__global__ void k_out(const float* __restrict__ x, float* __restrict__ out) {
    __shared__ float w[WIN];
    int b = blockIdx.y;
    int d = blockIdx.x * 256 + threadIdx.x;
    w[threadIdx.x] = g_w[b * WIN + threadIdx.x];
    __syncthreads();
    int L = g_len[b];
    size_t base = ((size_t)b * S_ + (size_t)(L - WIN)) * D_ + d;
    float acc = 0.f;
    for (int j = 0; j < WIN; j++) {
        float wj = w[j];
        if (wj != 0.f)   // ~43% of window weights underflow to exact 0
            acc += wj * x[base + (size_t)j * D_];
    }
    out[b * D_ + d] = acc;
}

// ---------------------------------------------------------------------------
extern "C" void kernel_launch(void* const* d_in, const int* in_sizes, int n_in,
                              void* d_out, int out_size) {
    const float* x   = (const float*)d_in[0];
    const unsigned char* mask = (const unsigned char*)d_in[1];
    const float* w1  = (const float*)d_in[2];
    const float* b1  = (const float*)d_in[3];
    const float* w2  = (const float*)d_in[4];
    const float* b2  = (const float*)d_in[5];
    const float* lam = (const float*)d_in[6];
    const float* q   = (const float*)d_in[7];
    const float* kw  = (const float*)d_in[8];
    const float* kb  = (const float*)d_in[9];
    float* out = (float*)d_out;
    (void)in_sizes; (void)n_in; (void)out_size;

    const int SMEM_P1 = MT * XSTRIDE * 2 + NC * WSTRIDE * 2
                      + (8 * MT + MT + MT) * (int)sizeof(float);
    cudaFuncSetAttribute(k_pass1, cudaFuncAttributeMaxDynamicSharedMemorySize, SMEM_P1);

    k_lengths<<<1, 256>>>(mask);
    k_prep_w<<<dim3(32, 16), dim3(32, 8)>>>(w1);
    k_prep_v<<<1025, 128>>>(kw, q, kb);
    k_pass1<<<128, 256, SMEM_P1>>>(x, b1, w2, b2);
    k_softmax<<<32, 256>>>(lam);
    k_out<<<dim3(4, 32), 256>>>(x, out);
}

// round 2
// speedup vs baseline: 1.9027x; 1.9027x over previous
#include <cuda_runtime.h>
#include <cuda_bf16.h>
#include <cstdint>

#define B_   32
#define S_   2048
#define D_   1024
#define N1_  512
#define WIN  256          // decay window: alpha underflows to exactly 0 outside
#define MT   64           // tokens per gemm block (M tile)
#define NC   128          // N-chunk per gemm block
#define KC   64           // K-chunk per pipeline stage
#define XPAD 72           // 64 + 8 bf16 pad (conflict-free fragment loads)

// -------- persistent device scratch (no dynamic allocation allowed) --------
__device__ __nv_bfloat16 g_Wt[N1_ * D_];        // W1 transposed bf16 [n][k]
__device__ __nv_bfloat16 g_xw[B_ * WIN * D_];   // windowed x, bf16 (16 MB)
__device__ float g_v[D_];                       // key_w @ q
__device__ float g_qkb;                         // q . key_b
__device__ int   g_len[B_];
__device__ int   g_flag[B_];                    // per-row multibyte-mask votes
__device__ float g_xv[B_ * WIN];                // x . v per window token
__device__ float g_gacc[B_ * WIN];              // gate pre-activation accum
__device__ float g_w[B_ * WIN];                 // alpha * gate

// ---------------------------------------------------------------------------
// Mask dtype probe: right-padding bool viewed as u8 is nondecreasing per row;
// wider-int encodings (01 00 00 00...) violate that. Also zeroes g_gacc.
// ---------------------------------------------------------------------------
__global__ void k_mode(const unsigned char* __restrict__ m8) {
    int tid = threadIdx.x, b = blockIdx.x;      // 32 x 256
    g_gacc[b * 256 + tid] = 0.f;
    const unsigned char* row = &m8[b * S_];
    int nm = 0;
    for (int i = tid; i < S_ - 1; i += 256)
        if (row[i] > row[i + 1]) nm = 1;
    nm = __syncthreads_or(nm);
    if (tid == 0) g_flag[b] = nm;
}

// Count valid (==0) elements per row; element width chosen by the probe.
// (u32 zero-count works identically for int32 and float32 masks.)
__global__ void k_len(const unsigned char* __restrict__ m8) {
    __shared__ int mb;
    __shared__ int part[8];
    int tid = threadIdx.x, b = blockIdx.x, lane = tid & 31, warp = tid >> 5;
    if (tid == 0) {
        int o = 0;
        for (int i = 0; i < B_; i++) o |= g_flag[i];
        mb = o;
    }
    __syncthreads();
    int c = 0;
    if (mb) {
        const unsigned* m32 = (const unsigned*)m8;
        for (int s = tid; s < S_; s += 256) if (m32[b * S_ + s] == 0u) c++;
    } else {
        for (int s = tid; s < S_; s += 256) if (m8[b * S_ + s] == 0) c++;
    }
    #pragma unroll
    for (int o = 16; o; o >>= 1) c += __shfl_xor_sync(0xffffffffu, c, o);
    if (lane == 0) part[warp] = c;
    __syncthreads();
    if (tid == 0) {
        int t = 0;
        #pragma unroll
        for (int w = 0; w < 8; w++) t += part[w];
        g_len[b] = t;
    }
}

// ---------------------------------------------------------------------------
// Transpose gate_w1 [K=1024][N=512] fp32 -> g_Wt [N][K] bf16
// ---------------------------------------------------------------------------
__global__ void k_prep_w(const float* __restrict__ w1) {
    __shared__ float t[32][33];
    int k0 = blockIdx.x * 32;               // 32
    int n0 = blockIdx.y * 32;               // 16
    int tx = threadIdx.x, ty = threadIdx.y; // (32, 8)
    #pragma unroll
    for (int i = 0; i < 4; i++)
        t[ty + i * 8][tx] = w1[(k0 + ty + i * 8) * N1_ + n0 + tx];
    __syncthreads();
    #pragma unroll
    for (int i = 0; i < 4; i++)
        g_Wt[(size_t)(n0 + ty + i * 8) * D_ + k0 + tx] =
            __float2bfloat16_rn(t[tx][ty + i * 8]);
}

// ---------------------------------------------------------------------------
// v = key_w @ q (fp32) and qkb = q . key_b
// ---------------------------------------------------------------------------
__global__ void k_prep_v(const float* __restrict__ kw, const float* __restrict__ q,
                         const float* __restrict__ kb) {
    int d = blockIdx.x, tid = threadIdx.x;  // 1025 x 128
    float p = 0.f;
    if (d < D_) {
        for (int e = tid; e < D_; e += 128) p += kw[(size_t)d * D_ + e] * q[e];
    } else {
        for (int e = tid; e < D_; e += 128) p += q[e] * kb[e];
    }
    #pragma unroll
    for (int o = 16; o; o >>= 1) p += __shfl_xor_sync(0xffffffffu, p, o);
    __shared__ float r[4];
    if ((tid & 31) == 0) r[tid >> 5] = p;
    __syncthreads();
    if (tid == 0) {
        float s = r[0] + r[1] + r[2] + r[3];
        if (d < D_) g_v[d] = s; else g_qkb = s;
    }
}

// ---------------------------------------------------------------------------
// Windowed x -> bf16 buffer + xv = x . v.  One warp per token, grid 1024.
// ---------------------------------------------------------------------------
__global__ void __launch_bounds__(256) k_prep_x(const float* __restrict__ x) {
    int token = blockIdx.x * 8 + (threadIdx.x >> 5);
    int lane = threadIdx.x & 31;
    int b = token >> 8, j = token & (WIN - 1);
    int L = g_len[b];
    const float* src = &x[((size_t)b * S_ + (size_t)(L - WIN) + j) * D_];
    __nv_bfloat16* dst = &g_xw[(size_t)token * D_];
    float acc = 0.f;
    #pragma unroll
    for (int i = 0; i < 8; i++) {
        int col = (i * 32 + lane) * 4;
        float4 xr = *(const float4*)&src[col];
        float4 v4 = *(const float4*)&g_v[col];
        acc += xr.x * v4.x + xr.y * v4.y + xr.z * v4.z + xr.w * v4.w;
        __nv_bfloat162 p0 = __floats2bfloat162_rn(xr.x, xr.y);
        __nv_bfloat162 p1 = __floats2bfloat162_rn(xr.z, xr.w);
        uint2 pk;
        pk.x = *(uint32_t*)&p0;
        pk.y = *(uint32_t*)&p1;
        *(uint2*)&dst[col] = pk;
    }
    #pragma unroll
    for (int o = 16; o; o >>= 1) acc += __shfl_xor_sync(0xffffffffu, acc, o);
    if (lane == 0) g_xv[token] = acc;
}

__device__ __forceinline__ float gelu_exact(float v) {
    return 0.5f * v * (1.0f + erff(v * 0.70710678118654752f));
}

__device__ __forceinline__ void cp16(void* s, const void* g) {
    uint32_t sa = (uint32_t)__cvta_generic_to_shared(s);
    asm volatile("cp.async.cg.shared.global [%0], [%1], 16;\n" :: "r"(sa), "l"(g));
}

// ---------------------------------------------------------------------------
// Gate-MLP GEMM, cp.async double-buffered.  grid = 512:
//   blk>>2 = token tile (b*4+part, 64 tokens), blk&3 = N-chunk of 128.
// Partial sum_n gelu(h+b1)*w2 accumulated to g_gacc via atomics.
// ---------------------------------------------------------------------------
__global__ void __launch_bounds__(256) k_gemm(
    const float* __restrict__ b1, const float* __restrict__ w2) {
    extern __shared__ char sm_[];
    __nv_bfloat16* xs = (__nv_bfloat16*)sm_;        // [2][MT][XPAD]
    __nv_bfloat16* ws = xs + 2 * MT * XPAD;         // [2][NC][XPAD]
    float* gacc = (float*)(ws + 2 * NC * XPAD);     // [MT]

    int tid = threadIdx.x, lane = tid & 31, warp = tid >> 5;
    int ncid = blockIdx.x & 3;
    int tile = blockIdx.x >> 2;                     // 0..127 == b*4+part
    const __nv_bfloat16* xbase = &g_xw[(size_t)tile * MT * D_];
    const __nv_bfloat16* wbase = &g_Wt[(size_t)ncid * NC * D_];
    if (tid < MT) gacc[tid] = 0.f;

    int wm = warp >> 2, wn = warp & 3;              // warp grid 2(M) x 4(N)
    int g4 = lane >> 2, q = lane & 3;

    float c[2][4][4];
    #pragma unroll
    for (int mf = 0; mf < 2; mf++)
        #pragma unroll
        for (int nf = 0; nf < 4; nf++)
            #pragma unroll
            for (int e = 0; e < 4; e++) c[mf][nf][e] = 0.f;

    // stage issuer: x chunk 64x64, W chunk 128x64 (bf16, 16B xfers)
    auto issue = [&](int kc, int st) {
        __nv_bfloat16* xd = xs + st * MT * XPAD;
        __nv_bfloat16* wd = ws + st * NC * XPAD;
        #pragma unroll
        for (int i = 0; i < 2; i++) {
            int idx = tid + i * 256;
            int r = idx >> 3, c8 = (idx & 7) << 3;
            cp16(&xd[r * XPAD + c8], &xbase[(size_t)r * D_ + kc * KC + c8]);
        }
        #pragma unroll
        for (int i = 0; i < 4; i++) {
            int idx = tid + i * 256;
            int r = idx >> 3, c8 = (idx & 7) << 3;
            cp16(&wd[r * XPAD + c8], &wbase[(size_t)r * D_ + kc * KC + c8]);
        }
        asm volatile("cp.async.commit_group;\n");
    };

    issue(0, 0);
    for (int kc = 0; kc < 16; kc++) {
        int st = kc & 1;
        if (kc < 15) {
            issue(kc + 1, st ^ 1);
            asm volatile("cp.async.wait_group 1;\n");
        } else {
            asm volatile("cp.async.wait_group 0;\n");
        }
        __syncthreads();
        const __nv_bfloat16* xb = xs + st * MT * XPAD;
        const __nv_bfloat16* wb = ws + st * NC * XPAD;
        #pragma unroll
        for (int kk = 0; kk < 4; kk++) {
            int kb_ = kk * 16 + q * 2;
            uint32_t a[2][4];
            #pragma unroll
            for (int mf = 0; mf < 2; mf++) {
                int r = wm * 32 + mf * 16 + g4;
                a[mf][0] = *(const uint32_t*)&xb[r * XPAD + kb_];
                a[mf][1] = *(const uint32_t*)&xb[(r + 8) * XPAD + kb_];
                a[mf][2] = *(const uint32_t*)&xb[r * XPAD + kb_ + 8];
                a[mf][3] = *(const uint32_t*)&xb[(r + 8) * XPAD + kb_ + 8];
            }
            uint32_t bb[4][2];
            #pragma unroll
            for (int nf = 0; nf < 4; nf++) {
                int n = wn * 32 + nf * 8 + g4;
                bb[nf][0] = *(const uint32_t*)&wb[n * XPAD + kb_];
                bb[nf][1] = *(const uint32_t*)&wb[n * XPAD + kb_ + 8];
            }
            #pragma unroll
            for (int mf = 0; mf < 2; mf++)
                #pragma unroll
                for (int nf = 0; nf < 4; nf++) {
                    asm volatile(
                        "mma.sync.aligned.m16n8k16.row.col.f32.bf16.bf16.f32 "
                        "{%0,%1,%2,%3}, {%4,%5,%6,%7}, {%8,%9}, {%0,%1,%2,%3};\n"
                        : "+f"(c[mf][nf][0]), "+f"(c[mf][nf][1]),
                          "+f"(c[mf][nf][2]), "+f"(c[mf][nf][3])
                        : "r"(a[mf][0]), "r"(a[mf][1]), "r"(a[mf][2]), "r"(a[mf][3]),
                          "r"(bb[nf][0]), "r"(bb[nf][1]));
                }
        }
        __syncthreads();
    }

    // epilogue: partial g[m] = sum_n gelu(h + b1[n]) * w2[n]
    #pragma unroll
    for (int mf = 0; mf < 2; mf++) {
        float lo = 0.f, hi = 0.f;
        #pragma unroll
        for (int nf = 0; nf < 4; nf++) {
            int n0 = ncid * NC + wn * 32 + nf * 8 + q * 2;
            float b1a = __ldg(&b1[n0]), b1b = __ldg(&b1[n0 + 1]);
            float w2a = __ldg(&w2[n0]), w2b = __ldg(&w2[n0 + 1]);
            lo += gelu_exact(c[mf][nf][0] + b1a) * w2a
                + gelu_exact(c[mf][nf][1] + b1b) * w2b;
            hi += gelu_exact(c[mf][nf][2] + b1a) * w2a
                + gelu_exact(c[mf][nf][3] + b1b) * w2b;
        }
        lo += __shfl_xor_sync(0xffffffffu, lo, 1);
        lo += __shfl_xor_sync(0xffffffffu, lo, 2);
        hi += __shfl_xor_sync(0xffffffffu, hi, 1);
        hi += __shfl_xor_sync(0xffffffffu, hi, 2);
        if (q == 0) {
            int r = wm * 32 + mf * 16 + g4;
            atomicAdd(&gacc[r], lo);
            atomicAdd(&gacc[r + 8], hi);
        }
    }
    __syncthreads();
    if (tid < MT) atomicAdd(&g_gacc[tile * MT + tid], gacc[tid]);
}

// ---------------------------------------------------------------------------
// sigmoid + logit + decayed window softmax; weights = alpha * gate
// ---------------------------------------------------------------------------
__global__ void k_finish(const float* __restrict__ b2, const float* __restrict__ lamp) {
    int b = blockIdx.x, tid = threadIdx.x;  // 32 x 256 (== WIN)
    int lane = tid & 31, warp = tid >> 5;
    __shared__ float redm[8], reds[8];

    float z = g_gacc[b * WIN + tid] + b2[0];
    float gate = 1.f / (1.f + expf(-z));
    float logit = (gate * g_xv[b * WIN + tid] + g_qkb) * 0.03125f;
    float lam = lamp[0];
    float pl = fmaxf(lam, 0.f) + log1pf(expf(-fabsf(lam)));  // softplus
    float dec = logit - pl * (float)(WIN - 1 - tid);         // = L-1-t in window

    float v = dec;
    #pragma unroll
    for (int o = 16; o; o >>= 1) v = fmaxf(v, __shfl_xor_sync(0xffffffffu, v, o));
    if (lane == 0) redm[warp] = v;
    __syncthreads();
    if (warp == 0) {
        float t = redm[lane & 7];
        #pragma unroll
        for (int o = 4; o; o >>= 1) t = fmaxf(t, __shfl_xor_sync(0xffffffffu, t, o));
        if (lane == 0) redm[0] = t;
    }
    __syncthreads();
    float m = redm[0];

    float e = expf(dec - m);
    v = e;
    #pragma unroll
    for (int o = 16; o; o >>= 1) v += __shfl_xor_sync(0xffffffffu, v, o);
    if (lane == 0) reds[warp] = v;
    __syncthreads();
    if (warp == 0) {
        float t = reds[lane & 7];
        #pragma unroll
        for (int o = 4; o; o >>= 1) t += __shfl_xor_sync(0xffffffffu, t, o);
        if (lane == 0) reds[0] = t;
    }
    __syncthreads();
    float s = reds[0];

    g_w[b * WIN + tid] = gate * e / s;
}

// ---------------------------------------------------------------------------
// scene[b,d] = sum_window w * x   (skip leading exactly-zero weights)
// ---------------------------------------------------------------------------
__global__ void k_out(const float* __restrict__ x, float* __restrict__ out) {
    __shared__ float w[WIN];
    __shared__ int j0s;
    int b = blockIdx.y;
    int d = blockIdx.x * 256 + threadIdx.x;
    w[threadIdx.x] = g_w[b * WIN + threadIdx.x];
    if (threadIdx.x == 0) j0s = WIN;
    __syncthreads();
    if (w[threadIdx.x] != 0.f) atomicMin(&j0s, (int)threadIdx.x);
    __syncthreads();
    int j0 = j0s;
    int L = g_len[b];
    size_t base = ((size_t)b * S_ + (size_t)(L - WIN)) * D_ + d;
    float a0 = 0.f, a1 = 0.f, a2 = 0.f, a3 = 0.f;
    int j = j0;
    for (; j + 3 < WIN; j += 4) {
        a0 = fmaf(w[j],     x[base + (size_t)j * D_],       a0);
        a1 = fmaf(w[j + 1], x[base + (size_t)(j + 1) * D_], a1);
        a2 = fmaf(w[j + 2], x[base + (size_t)(j + 2) * D_], a2);
        a3 = fmaf(w[j + 3], x[base + (size_t)(j + 3) * D_], a3);
    }
    for (; j < WIN; j++) a0 = fmaf(w[j], x[base + (size_t)j * D_], a0);
    out[b * D_ + d] = (a0 + a1) + (a2 + a3);
}

// ---------------------------------------------------------------------------
extern "C" void kernel_launch(void* const* d_in, const int* in_sizes, int n_in,
                              void* d_out, int out_size) {
    const float* x   = (const float*)d_in[0];
    const unsigned char* mask = (const unsigned char*)d_in[1];
    const float* w1  = (const float*)d_in[2];
    const float* b1  = (const float*)d_in[3];
    const float* w2  = (const float*)d_in[4];
    const float* b2  = (const float*)d_in[5];
    const float* lam = (const float*)d_in[6];
    const float* q   = (const float*)d_in[7];
    const float* kw  = (const float*)d_in[8];
    const float* kb  = (const float*)d_in[9];
    float* out = (float*)d_out;
    (void)in_sizes; (void)n_in; (void)out_size;

    const int SMEM_G = (2 * MT * XPAD + 2 * NC * XPAD) * 2 + MT * (int)sizeof(float);
    cudaFuncSetAttribute(k_gemm, cudaFuncAttributeMaxDynamicSharedMemorySize, SMEM_G);

    k_mode<<<32, 256>>>(mask);
    k_len<<<32, 256>>>(mask);
    k_prep_w<<<dim3(32, 16), dim3(32, 8)>>>(w1);
    k_prep_v<<<1025, 128>>>(kw, q, kb);
    k_prep_x<<<1024, 256>>>(x);
    k_gemm<<<512, 256, SMEM_G>>>(b1, w2);
    k_finish<<<32, 256>>>(b2, lam);
    k_out<<<dim3(4, 32), 256>>>(x, out);
}